// round 1
// baseline (speedup 1.0000x reference)
#include <cuda_runtime.h>

#define BATCH 65536
#define TSTEPS 32
#define F 33
#define H 24

// Scratch for x_spatial [B, 90, 12] (row-major, contiguous per sample).
__device__ __align__(16) float g_xsp[(size_t)BATCH * 1080];

// ---------------------------------------------------------------------------
// Kernel A: conv1+bn1+relu -> conv2+bn2+relu, producing x_spatial[b][s][c].
// One thread per (b, s): reads x[4s-4 .. 4s+4], writes 12 channels.
// ---------------------------------------------------------------------------
__global__ __launch_bounds__(256) void conv_kernel(
    const float* __restrict__ x,
    const float* __restrict__ w1, const float* __restrict__ cb1,
    const float* __restrict__ g1, const float* __restrict__ bb1,
    const float* __restrict__ m1, const float* __restrict__ v1,
    const float* __restrict__ w2, const float* __restrict__ cb2,
    const float* __restrict__ g2, const float* __restrict__ bb2,
    const float* __restrict__ m2, const float* __restrict__ v2)
{
    __shared__ float sw1[30], sw2[216], ss1[6], sbe1[6], ss2[12], sbe2[12];
    int tx = threadIdx.x;
    if (tx < 30)  sw1[tx] = w1[tx];
    if (tx < 216) sw2[tx] = w2[tx];
    if (tx < 6) {
        float sc = g1[tx] * rsqrtf(v1[tx] + 1e-5f);
        ss1[tx]  = sc;
        sbe1[tx] = bb1[tx] + sc * (cb1[tx] - m1[tx]);
    }
    if (tx >= 32 && tx < 44) {
        int c = tx - 32;
        float sc = g2[c] * rsqrtf(v2[c] + 1e-5f);
        ss2[c]  = sc;
        sbe2[c] = bb2[c] + sc * (cb2[c] - m2[c]);
    }
    __syncthreads();

    unsigned gid = blockIdx.x * 256u + (unsigned)tx;   // 0 .. B*90-1 (exact)
    unsigned b = gid / 90u;
    int s = (int)(gid % 90u);

    const float* xb = x + (size_t)b * 360;
    float xv[9];
    int base = 4 * s - 4;
#pragma unroll
    for (int i = 0; i < 9; i++) {
        int idx = base + i;
        xv[i] = (idx >= 0 && idx < 360) ? __ldg(xb + idx) : 0.f;
    }

    // h1 at positions p = 2s-1 .. 2s+1 (conv2 pad=1); p=-1 only at s=0,q=0.
    float h1v[6][3];
#pragma unroll
    for (int q = 0; q < 3; q++) {
        bool valid = (2 * s - 1 + q) >= 0;
#pragma unroll
        for (int c = 0; c < 6; c++) {
            float a = 0.f;
#pragma unroll
            for (int k = 0; k < 5; k++) a = fmaf(sw1[c * 5 + k], xv[2 * q + k], a);
            a = ss1[c] * a + sbe1[c];
            h1v[c][q] = valid ? fmaxf(a, 0.f) : 0.f;
        }
    }

    float* o = g_xsp + (size_t)b * 1080 + s * 12;
#pragma unroll
    for (int c2 = 0; c2 < 12; c2++) {
        float a = 0.f;
#pragma unroll
        for (int c1 = 0; c1 < 6; c1++)
#pragma unroll
            for (int q = 0; q < 3; q++)
                a = fmaf(sw2[(c2 * 6 + c1) * 3 + q], h1v[c1][q], a);
        a = ss2[c2] * a + sbe2[c2];
        o[c2] = fmaxf(a, 0.f);
    }
}

// ---------------------------------------------------------------------------
// Kernel B: LIF x2 + LSTM + head, one thread per sample.
// ---------------------------------------------------------------------------
__device__ __forceinline__ float sigf(float x) {
    return __fdividef(1.f, 1.f + __expf(-x));
}
__device__ __forceinline__ float tanhfast(float x) {
    float e = __expf(2.f * x);
    return 1.f - __fdividef(2.f, e + 1.f);   // correct limits at +/-inf
}

__global__ __launch_bounds__(256) void lstm_head_kernel(
    const float* __restrict__ wih, const float* __restrict__ whh,
    const float* __restrict__ bih, const float* __restrict__ bhh,
    const float* __restrict__ rtw1, const float* __restrict__ rtb1,
    const float* __restrict__ rtw2, const float* __restrict__ rtb2,
    const float* __restrict__ fw,  const float* __restrict__ fb,
    const float* __restrict__ cw1, const float* __restrict__ cb1_,
    const float* __restrict__ cw2, const float* __restrict__ cb2_,
    float* __restrict__ out)
{
    // Gate-packed weights: one float4 = {Wi, Wf, Wg, Wo} row element -> LDS.128
    __shared__ float4 sWp[F * 24];     // [k][j]
    __shared__ float4 sHp[24 * 24];    // [k][j]
    __shared__ float4 sBs[24];
    __shared__ float s_rtw1[12 * 36], s_rtb1[12], s_rtw2[24], s_rtb2[2];
    __shared__ float s_fw[24 * 36], s_fb[24];
    __shared__ float s_cw1[12 * 24], s_cb1[12], s_cw2[60], s_cb2[5];

    int tx = threadIdx.x;
    for (int i = tx; i < F * 24; i += 256) {
        int k = i / 24, j = i % 24;
        sWp[i] = make_float4(wih[j * F + k], wih[(24 + j) * F + k],
                             wih[(48 + j) * F + k], wih[(72 + j) * F + k]);
    }
    for (int i = tx; i < 24 * 24; i += 256) {
        int k = i / 24, j = i % 24;
        sHp[i] = make_float4(whh[j * 24 + k], whh[(24 + j) * 24 + k],
                             whh[(48 + j) * 24 + k], whh[(72 + j) * 24 + k]);
    }
    if (tx < 24)
        sBs[tx] = make_float4(bih[tx] + bhh[tx], bih[24 + tx] + bhh[24 + tx],
                              bih[48 + tx] + bhh[48 + tx], bih[72 + tx] + bhh[72 + tx]);
    for (int i = tx; i < 432; i += 256) s_rtw1[i] = rtw1[i];
    if (tx < 12) s_rtb1[tx] = rtb1[tx];
    if (tx < 24) s_rtw2[tx] = rtw2[tx];
    if (tx < 2)  s_rtb2[tx] = rtb2[tx];
    for (int i = tx; i < 864; i += 256) s_fw[i] = fw[i];
    if (tx < 24) s_fb[tx] = fb[tx];
    for (int i = tx; i < 288; i += 256) s_cw1[i] = cw1[i];
    if (tx < 12) s_cb1[tx] = cb1_[tx];
    if (tx < 60) s_cw2[tx] = cw2[tx];
    if (tx < 5)  s_cb2[tx] = cb2_[tx];
    __syncthreads();

    unsigned b = blockIdx.x * 256u + (unsigned)tx;
    const float* fl = g_xsp + (size_t)b * 1080;

    float mem1[F], mem2[F], h[H], c[H];
#pragma unroll
    for (int k = 0; k < F; k++) { mem1[k] = 0.f; mem2[k] = 0.f; }
#pragma unroll
    for (int j = 0; j < H; j++) { h[j] = 0.f; c[j] = 0.f; }

#pragma unroll 1
    for (int t = 0; t < TSTEPS; t++) {
        const float* xt = fl + t * F;
        float sp[F];
#pragma unroll
        for (int k = 0; k < F; k++) {
            float in = __ldg(xt + k);
            float a = 0.95f * mem1[k] + in;
            float s1 = (a > 0.5f) ? 1.f : 0.f;
            mem1[k] = a * (1.f - s1);
            float bm = 0.9f * mem2[k] + s1;
            float s2 = (bm > 0.6f) ? 1.f : 0.f;
            mem2[k] = bm * (1.f - s2);
            sp[k] = s2;
        }
        float hn[H];
#pragma unroll
        for (int j = 0; j < H; j++) {
            float4 a = sBs[j];
#pragma unroll
            for (int k = 0; k < F; k++) {
                float4 w = sWp[k * 24 + j];
                float f = sp[k];
                a.x = fmaf(f, w.x, a.x);
                a.y = fmaf(f, w.y, a.y);
                a.z = fmaf(f, w.z, a.z);
                a.w = fmaf(f, w.w, a.w);
            }
#pragma unroll
            for (int k = 0; k < H; k++) {
                float4 w = sHp[k * 24 + j];
                float f = h[k];
                a.x = fmaf(f, w.x, a.x);
                a.y = fmaf(f, w.y, a.y);
                a.z = fmaf(f, w.z, a.z);
                a.w = fmaf(f, w.w, a.w);
            }
            float gi = sigf(a.x);
            float gf = sigf(a.y);
            float gg = tanhfast(a.z);
            float go = sigf(a.w);
            c[j] = gf * c[j] + gi * gg;
            hn[j] = go * tanhfast(c[j]);
        }
#pragma unroll
        for (int j = 0; j < H; j++) h[j] = hn[j];
    }

    // spatial average over all 90 positions
    float avg[12];
#pragma unroll
    for (int i = 0; i < 12; i++) avg[i] = 0.f;
    const float4* x4 = reinterpret_cast<const float4*>(fl);
#pragma unroll 1
    for (int s = 0; s < 90; s++) {
        float4 a0 = __ldg(x4 + s * 3);
        float4 a1 = __ldg(x4 + s * 3 + 1);
        float4 a2 = __ldg(x4 + s * 3 + 2);
        avg[0] += a0.x; avg[1] += a0.y; avg[2]  += a0.z; avg[3]  += a0.w;
        avg[4] += a1.x; avg[5] += a1.y; avg[6]  += a1.z; avg[7]  += a1.w;
        avg[8] += a2.x; avg[9] += a2.y; avg[10] += a2.z; avg[11] += a2.w;
    }
#pragma unroll
    for (int i = 0; i < 12; i++) avg[i] *= (1.f / 90.f);

    float comb[36];
#pragma unroll
    for (int j = 0; j < 24; j++) comb[j] = h[j];
#pragma unroll
    for (int i = 0; i < 12; i++) comb[24 + i] = avg[i];

    float z1[12];
#pragma unroll
    for (int i = 0; i < 12; i++) {
        float a = s_rtb1[i];
#pragma unroll
        for (int k = 0; k < 36; k++) a = fmaf(s_rtw1[i * 36 + k], comb[k], a);
        z1[i] = fmaxf(a, 0.f);
    }
    float z2[2];
#pragma unroll
    for (int i = 0; i < 2; i++) {
        float a = s_rtb2[i];
#pragma unroll
        for (int k = 0; k < 12; k++) a = fmaf(s_rtw2[i * 12 + k], z1[k], a);
        z2[i] = a;
    }
    float mx = fmaxf(z2[0], z2[1]);
    float e0 = __expf(z2[0] - mx), e1 = __expf(z2[1] - mx);
    float inv = 1.f / (e0 + e1);
    float rw0 = 0.7f * (e0 * inv), rw1 = 0.3f * (e1 * inv);
    float alpha = rw0 / (rw0 + rw1);

    float fin[36];
#pragma unroll
    for (int j = 0; j < 24; j++) fin[j] = h[j] * alpha;
    float om = 1.f - alpha;
#pragma unroll
    for (int i = 0; i < 12; i++) fin[24 + i] = avg[i] * om;

    float fused[24];
#pragma unroll
    for (int i = 0; i < 24; i++) {
        float a = s_fb[i];
#pragma unroll
        for (int k = 0; k < 36; k++) a = fmaf(s_fw[i * 36 + k], fin[k], a);
        fused[i] = fmaxf(a, 0.f);
    }
    float y1[12];
#pragma unroll
    for (int i = 0; i < 12; i++) {
        float a = s_cb1[i];
#pragma unroll
        for (int k = 0; k < 24; k++) a = fmaf(s_cw1[i * 24 + k], fused[k], a);
        y1[i] = fmaxf(a, 0.f);
    }
    float* ob = out + (size_t)b * 5;
#pragma unroll
    for (int i = 0; i < 5; i++) {
        float a = s_cb2[i];
#pragma unroll
        for (int k = 0; k < 12; k++) a = fmaf(s_cw2[i * 12 + k], y1[k], a);
        ob[i] = a;
    }
}

extern "C" void kernel_launch(void* const* d_in, const int* in_sizes, int n_in,
                              void* d_out, int out_size) {
    const float* x   = (const float*)d_in[0];
    const float* c1w = (const float*)d_in[1];
    const float* c1b = (const float*)d_in[2];
    const float* b1g = (const float*)d_in[3];
    const float* b1b = (const float*)d_in[4];
    const float* b1m = (const float*)d_in[5];
    const float* b1v = (const float*)d_in[6];
    const float* c2w = (const float*)d_in[7];
    const float* c2b = (const float*)d_in[8];
    const float* b2g = (const float*)d_in[9];
    const float* b2b = (const float*)d_in[10];
    const float* b2m = (const float*)d_in[11];
    const float* b2v = (const float*)d_in[12];
    const float* wih = (const float*)d_in[13];
    const float* whh = (const float*)d_in[14];
    const float* bih = (const float*)d_in[15];
    const float* bhh = (const float*)d_in[16];
    const float* rtw1 = (const float*)d_in[17];
    const float* rtb1 = (const float*)d_in[18];
    const float* rtw2 = (const float*)d_in[19];
    const float* rtb2 = (const float*)d_in[20];
    const float* fw  = (const float*)d_in[21];
    const float* fb  = (const float*)d_in[22];
    const float* cw1 = (const float*)d_in[23];
    const float* cb1 = (const float*)d_in[24];
    const float* cw2 = (const float*)d_in[25];
    const float* cb2 = (const float*)d_in[26];
    float* out = (float*)d_out;

    // B*90 = 5,898,240 threads -> exactly 23040 blocks of 256
    conv_kernel<<<23040, 256>>>(x, c1w, c1b, b1g, b1b, b1m, b1v,
                                c2w, c2b, b2g, b2b, b2m, b2v);
    // B = 65536 threads -> 256 blocks of 256
    lstm_head_kernel<<<256, 256>>>(wih, whh, bih, bhh,
                                   rtw1, rtb1, rtw2, rtb2,
                                   fw, fb, cw1, cb1, cw2, cb2, out);
}